// round 4
// baseline (speedup 1.0000x reference)
#include <cuda_runtime.h>
#include <math.h>

#define BB 64
#define SS 1024
#define DD 128
#define HH 20
#define G4 80   // 4*H

// ---------------- scratch (device globals; no allocations) ----------------
__device__ float g_G[BB * SS * G4];   // input-gemm result + bias   (~21 MB)
__device__ float g_HS[BB * SS * HH];  // LSTM hidden states         (~5.2 MB)
__device__ float g_A[BB * SS];
__device__ float g_Cst[BB * SS];
__device__ float g_Sig[BB * SS];
__device__ float g_Mu[BB * SS];

__device__ __forceinline__ float sigmoidf_(float x) {
    return 1.0f / (1.0f + __expf(-x));
}

// ---------------- K1: G[bs,k] = x[bs,:] . W_ih[k,:] + b_ih[k] + b_hh[k] ----
// M = 65536, N = 80, K = 128. Tile: 64 rows x 80 cols, K chunked by 32.
__global__ void k1_ingemm(const float* __restrict__ x,
                          const float* __restrict__ Wih,
                          const float* __restrict__ bih,
                          const float* __restrict__ bhh) {
    __shared__ float xs[64][33];   // +1 pad: kill bank conflicts
    __shared__ float wsm[80][33];

    const int tid  = threadIdx.x;          // 256 threads
    const int row0 = blockIdx.x * 64;
    const int ty   = tid >> 4;             // 0..15 -> 4 rows each
    const int tx   = tid & 15;             // 0..15 -> 5 cols each

    float acc[4][5];
#pragma unroll
    for (int i = 0; i < 4; i++)
#pragma unroll
        for (int j = 0; j < 5; j++) acc[i][j] = 0.0f;

    for (int kc = 0; kc < 128; kc += 32) {
        __syncthreads();
        // stage x chunk: 64 rows x 32 cols (float4 global loads)
        for (int i = tid; i < 64 * 8; i += 256) {
            int r = i >> 3, c4 = i & 7;
            float4 v = *(const float4*)&x[(size_t)(row0 + r) * 128 + kc + c4 * 4];
            xs[r][c4 * 4 + 0] = v.x; xs[r][c4 * 4 + 1] = v.y;
            xs[r][c4 * 4 + 2] = v.z; xs[r][c4 * 4 + 3] = v.w;
        }
        // stage W chunk: 80 rows x 32 cols
        for (int i = tid; i < 80 * 8; i += 256) {
            int r = i >> 3, c4 = i & 7;
            float4 v = *(const float4*)&Wih[(size_t)r * 128 + kc + c4 * 4];
            wsm[r][c4 * 4 + 0] = v.x; wsm[r][c4 * 4 + 1] = v.y;
            wsm[r][c4 * 4 + 2] = v.z; wsm[r][c4 * 4 + 3] = v.w;
        }
        __syncthreads();

#pragma unroll 8
        for (int k = 0; k < 32; k++) {
            float xa[4], wb[5];
#pragma unroll
            for (int i = 0; i < 4; i++) xa[i] = xs[ty * 4 + i][k];
#pragma unroll
            for (int j = 0; j < 5; j++) wb[j] = wsm[tx * 5 + j][k];
#pragma unroll
            for (int i = 0; i < 4; i++)
#pragma unroll
                for (int j = 0; j < 5; j++)
                    acc[i][j] = fmaf(xa[i], wb[j], acc[i][j]);
        }
    }

#pragma unroll
    for (int i = 0; i < 4; i++) {
        int r = row0 + ty * 4 + i;
#pragma unroll
        for (int j = 0; j < 5; j++) {
            int c = tx * 5 + j;
            g_G[(size_t)r * G4 + c] = acc[i][j] + __ldg(&bih[c]) + __ldg(&bhh[c]);
        }
    }
}

// ---------------- K2: LSTM recurrence (1 block of 128 threads per batch) ---
__global__ void k2_lstm(const float* __restrict__ Whh) {
    const int b = blockIdx.x;
    const int k = threadIdx.x;      // 0..127 ; gates use k < 80

    __shared__ float sh[HH];        // h_t
    __shared__ float sg[G4];        // gate pre-activations

    float w[HH];
    if (k < G4) {
#pragma unroll
        for (int m = 0; m < HH; m++) w[m] = Whh[k * HH + m];
    }
    float c = 0.0f;
    if (k < HH) sh[k] = 0.0f;
    __syncthreads();

    const float* Gb = g_G + (size_t)b * SS * G4;
    float gin0 = (k < G4) ? Gb[k] : 0.0f;
    float gin1 = (k < G4) ? Gb[G4 + k] : 0.0f;

    for (int s = 0; s < SS; s++) {
        float gin2 = 0.0f;
        if (k < G4 && s + 2 < SS) gin2 = Gb[(size_t)(s + 2) * G4 + k];

        if (k < G4) {
            float a0 = gin0, a1 = 0.0f, a2 = 0.0f, a3 = 0.0f;
#pragma unroll
            for (int m = 0; m < HH; m += 4) {
                a0 = fmaf(w[m + 0], sh[m + 0], a0);
                a1 = fmaf(w[m + 1], sh[m + 1], a1);
                a2 = fmaf(w[m + 2], sh[m + 2], a2);
                a3 = fmaf(w[m + 3], sh[m + 3], a3);
            }
            sg[k] = (a0 + a1) + (a2 + a3);
        }
        __syncthreads();

        if (k < HH) {
            float ig = sigmoidf_(sg[k]);
            float fg = sigmoidf_(sg[HH + k]);
            float gg = tanhf(sg[2 * HH + k]);
            float og = sigmoidf_(sg[3 * HH + k]);
            c = fmaf(fg, c, ig * gg);
            float hn = og * tanhf(c);
            sh[k] = hn;
            g_HS[((size_t)b * SS + s) * HH + k] = hn;
        }
        __syncthreads();
        gin0 = gin1; gin1 = gin2;
    }
}

// ---------------- K3: per-(b,s) heads -> a, cst, sigma ---------------------
__global__ void k3_proj(const float* __restrict__ Wmu, const float* __restrict__ bmu,
                        const float* __restrict__ Wsig, const float* __restrict__ bsig) {
    const int idx = blockIdx.x * 256 + threadIdx.x;   // 0..65535
    const float* h = g_HS + (size_t)idx * HH;

    float d0 = __ldg(&bmu[0]), d1 = __ldg(&bmu[1]), d2 = __ldg(&bmu[2]);
    float ds = __ldg(&bsig[0]);
#pragma unroll
    for (int m = 0; m < HH; m++) {
        float hv = h[m];
        d0 = fmaf(__ldg(&Wmu[m]),          hv, d0);
        d1 = fmaf(__ldg(&Wmu[HH + m]),     hv, d1);
        d2 = fmaf(__ldg(&Wmu[2 * HH + m]), hv, d2);
        ds = fmaf(__ldg(&Wsig[m]),         hv, ds);
    }
    float a  = fmaxf(d0, 0.0f);
    float m1 = fmaxf(d1, 0.0f);
    float m2 = fmaxf(d2, 0.0f);

    const int j = idx & (SS - 1);
    g_A[idx]   = a;
    g_Cst[idx] = m1 * (1.0f / SS) + m2 * ((float)(j + 1) * (1.0f / SS));
    g_Sig[idx] = sigmoidf_(ds);
}

// ---------------- K4: mu scan (1 thread per batch) -------------------------
__global__ void k4_mu() {
    const int b = threadIdx.x;    // 64 threads
    const float* A = g_A + (size_t)b * SS;
    const float* C = g_Cst + (size_t)b * SS;
    float* M = g_Mu + (size_t)b * SS;
    float mu = 0.0f;
#pragma unroll 4
    for (int j = 0; j < SS; j++) {
        mu = fmaf(A[j], mu, C[j]);
        M[j] = mu;
    }
}

// ---------------- K5: triangular weighted sum + L2 normalization -----------
// grid (16, 64): blockIdx.y = b, j-tile index = 15 - blockIdx.x (heavy first)
__global__ void __launch_bounds__(256) k5_attn(const float* __restrict__ x,
                                               float* __restrict__ out) {
    __shared__ __align__(16) float xs[64][128];   // 32 KB
    __shared__ __align__(16) float ws[64][64];    // 16 KB  (total = 48 KB)

    const int tid = threadIdx.x;
    const int b   = blockIdx.y;
    const int jt  = (int)gridDim.x - 1 - (int)blockIdx.x;
    const int j0  = jt * 64;

    // w-producer role
    const int wj    = tid & 63;
    const int chunk = tid >> 6;            // 0..3, each covers 16 t's per tile
    const int jg    = j0 + wj;
    const float mu     = g_Mu[(size_t)b * SS + jg];
    const float sgv    = g_Sig[(size_t)b * SS + jg];
    const float inv2s2 = 1.0f / (2.0f * sgv * sgv);
    const float invj1  = 1.0f / (float)(jg + 1);
    float w2 = 0.0f;

    // GEMM role: 4 j's x 8 d's per thread
    const int jl0 = (tid & 15) * 4;
    const int dd0 = (tid >> 4) * 8;
    float acc[4][8];
#pragma unroll
    for (int i = 0; i < 4; i++)
#pragma unroll
        for (int j = 0; j < 8; j++) acc[i][j] = 0.0f;

    const float4* xg4 = (const float4*)(x + (size_t)b * SS * DD);

    for (int tt = 0; tt <= jt; tt++) {
        const int t0 = tt * 64;
        __syncthreads();   // protect xs/ws from previous tile's readers

        // stage x[b, t0..t0+63, :] (coalesced float4)
#pragma unroll
        for (int i = 0; i < 8; i++) {
            int idx = tid + i * 256;       // 0..2047 float4s
            ((float4*)xs)[idx] = xg4[t0 * 32 + idx];
        }
        // compute 64x64 w-tile (stored [t][j]); accumulate w^2 in registers
#pragma unroll
        for (int it = 0; it < 16; it++) {
            int tl = chunk * 16 + it;
            int t  = t0 + tl;
            float dlt = fmaf((float)t, invj1, -mu);
            float e   = dlt * dlt * inv2s2;
            float wv  = (t <= jg) ? __expf(-e) : 0.0f;
            ws[tl][wj] = wv;
            w2 = fmaf(wv, wv, w2);
        }
        __syncthreads();

        // register-tiled GEMM: acc[j][d] += w[t][j] * x[t][d]
#pragma unroll 8
        for (int t = 0; t < 64; t++) {
            float4 wv = *(const float4*)&ws[t][jl0];
            float4 x0 = *(const float4*)&xs[t][dd0];
            float4 x1 = *(const float4*)&xs[t][dd0 + 4];
            float wr[4] = {wv.x, wv.y, wv.z, wv.w};
            float xr[8] = {x0.x, x0.y, x0.z, x0.w, x1.x, x1.y, x1.z, x1.w};
#pragma unroll
            for (int jj = 0; jj < 4; jj++)
#pragma unroll
                for (int dd = 0; dd < 8; dd++)
                    acc[jj][dd] = fmaf(wr[jj], xr[dd], acc[jj][dd]);
        }
    }

    // reduce w^2 across the 4 chunks (reuse ws smem), then write normalized out
    __syncthreads();
    float* w2p = &ws[0][0];
    w2p[chunk * 64 + wj] = w2;
    __syncthreads();

#pragma unroll
    for (int jj = 0; jj < 4; jj++) {
        int jl = jl0 + jj;
        float s2  = w2p[jl] + w2p[64 + jl] + w2p[128 + jl] + w2p[192 + jl];
        float inv = 1.0f / fmaxf(sqrtf(s2), 1e-12f);
        float4 o0, o1;
        o0.x = acc[jj][0] * inv; o0.y = acc[jj][1] * inv;
        o0.z = acc[jj][2] * inv; o0.w = acc[jj][3] * inv;
        o1.x = acc[jj][4] * inv; o1.y = acc[jj][5] * inv;
        o1.z = acc[jj][6] * inv; o1.w = acc[jj][7] * inv;
        size_t base = ((size_t)b * SS + (j0 + jl)) * DD + dd0;
        *(float4*)&out[base]     = o0;
        *(float4*)&out[base + 4] = o1;
    }
}

// ---------------- launch ---------------------------------------------------
extern "C" void kernel_launch(void* const* d_in, const int* in_sizes, int n_in,
                              void* d_out, int out_size) {
    const float* x    = (const float*)d_in[0];
    const float* Wih  = (const float*)d_in[1];
    const float* Whh  = (const float*)d_in[2];
    const float* bih  = (const float*)d_in[3];
    const float* bhh  = (const float*)d_in[4];
    const float* Wmu  = (const float*)d_in[5];
    const float* bmu  = (const float*)d_in[6];
    const float* Wsig = (const float*)d_in[7];
    const float* bsig = (const float*)d_in[8];
    float* out = (float*)d_out;

    k1_ingemm<<<(BB * SS) / 64, 256>>>(x, Wih, bih, bhh);
    k2_lstm<<<BB, 128>>>(Whh);
    k3_proj<<<(BB * SS) / 256, 256>>>(Wmu, bmu, Wsig, bsig);
    k4_mu<<<1, BB>>>();
    k5_attn<<<dim3(SS / 64, BB), 256>>>(x, out);
}

// round 9
// speedup vs baseline: 1.3922x; 1.3922x over previous
#include <cuda_runtime.h>
#include <math.h>

#define BB 64
#define SS 1024
#define DD 128
#define HH 20
#define G4 80   // 4*H

// ---------------- scratch (device globals; no allocations) ----------------
__device__ float g_G[BB * SS * G4];   // input-gemm result + bias   (~21 MB)
__device__ float g_HS[BB * SS * HH];  // LSTM hidden states         (~5.2 MB)
__device__ float g_Sig[BB * SS];
__device__ float g_Mu[BB * SS];

__device__ __forceinline__ float sigmoidf_(float x) {
    return __fdividef(1.0f, 1.0f + __expf(-x));
}

// fast tanh via exp2-based __expf; clamp keeps e finite (c is gate-bounded anyway)
__device__ __forceinline__ float tanhf_fast(float x) {
    float xc = fminf(fmaxf(x, -15.0f), 15.0f);
    float e  = __expf(2.0f * xc);
    return __fdividef(e - 1.0f, e + 1.0f);
}

// ---------------- K1: G[bs,k] = x[bs,:] . W_ih[k,:] + b_ih[k] + b_hh[k] ----
// M = 65536, N = 80, K = 128. Tile: 64 rows x 80 cols, K chunked by 32.
__global__ void k1_ingemm(const float* __restrict__ x,
                          const float* __restrict__ Wih,
                          const float* __restrict__ bih,
                          const float* __restrict__ bhh) {
    __shared__ float xs[64][33];   // +1 pad: kill bank conflicts
    __shared__ float wsm[80][33];

    const int tid  = threadIdx.x;          // 256 threads
    const int row0 = blockIdx.x * 64;
    const int ty   = tid >> 4;             // 0..15 -> 4 rows each
    const int tx   = tid & 15;             // 0..15 -> 5 cols each

    float acc[4][5];
#pragma unroll
    for (int i = 0; i < 4; i++)
#pragma unroll
        for (int j = 0; j < 5; j++) acc[i][j] = 0.0f;

    for (int kc = 0; kc < 128; kc += 32) {
        __syncthreads();
        for (int i = tid; i < 64 * 8; i += 256) {
            int r = i >> 3, c4 = i & 7;
            float4 v = *(const float4*)&x[(size_t)(row0 + r) * 128 + kc + c4 * 4];
            xs[r][c4 * 4 + 0] = v.x; xs[r][c4 * 4 + 1] = v.y;
            xs[r][c4 * 4 + 2] = v.z; xs[r][c4 * 4 + 3] = v.w;
        }
        for (int i = tid; i < 80 * 8; i += 256) {
            int r = i >> 3, c4 = i & 7;
            float4 v = *(const float4*)&Wih[(size_t)r * 128 + kc + c4 * 4];
            wsm[r][c4 * 4 + 0] = v.x; wsm[r][c4 * 4 + 1] = v.y;
            wsm[r][c4 * 4 + 2] = v.z; wsm[r][c4 * 4 + 3] = v.w;
        }
        __syncthreads();

#pragma unroll 8
        for (int k = 0; k < 32; k++) {
            float xa[4], wb[5];
#pragma unroll
            for (int i = 0; i < 4; i++) xa[i] = xs[ty * 4 + i][k];
#pragma unroll
            for (int j = 0; j < 5; j++) wb[j] = wsm[tx * 5 + j][k];
#pragma unroll
            for (int i = 0; i < 4; i++)
#pragma unroll
                for (int j = 0; j < 5; j++)
                    acc[i][j] = fmaf(xa[i], wb[j], acc[i][j]);
        }
    }

#pragma unroll
    for (int i = 0; i < 4; i++) {
        int r = row0 + ty * 4 + i;
#pragma unroll
        for (int j = 0; j < 5; j++) {
            int c = tx * 5 + j;
            g_G[(size_t)r * G4 + c] = acc[i][j] + __ldg(&bih[c]) + __ldg(&bhh[c]);
        }
    }
}

// ---------------- K2: LSTM recurrence (1 block of 128 threads per batch) ---
__global__ void k2_lstm(const float* __restrict__ Whh) {
    const int b = blockIdx.x;
    const int k = threadIdx.x;      // 0..127 ; gates use k < 80

    __shared__ float sh[HH];        // h_t
    __shared__ float sg[G4];        // gate pre-activations

    float w[HH];
    if (k < G4) {
#pragma unroll
        for (int m = 0; m < HH; m++) w[m] = Whh[k * HH + m];
    }
    float c = 0.0f;
    if (k < HH) sh[k] = 0.0f;
    __syncthreads();

    const float* Gb = g_G + (size_t)b * SS * G4;
    float gin0 = (k < G4) ? Gb[k] : 0.0f;
    float gin1 = (k < G4) ? Gb[G4 + k] : 0.0f;

    for (int s = 0; s < SS; s++) {
        float gin2 = 0.0f;
        if (k < G4 && s + 2 < SS) gin2 = Gb[(size_t)(s + 2) * G4 + k];

        if (k < G4) {
            float a0 = gin0, a1 = 0.0f, a2 = 0.0f, a3 = 0.0f;
#pragma unroll
            for (int m = 0; m < HH; m += 4) {
                a0 = fmaf(w[m + 0], sh[m + 0], a0);
                a1 = fmaf(w[m + 1], sh[m + 1], a1);
                a2 = fmaf(w[m + 2], sh[m + 2], a2);
                a3 = fmaf(w[m + 3], sh[m + 3], a3);
            }
            sg[k] = (a0 + a1) + (a2 + a3);
        }
        __syncthreads();

        if (k < HH) {
            float ig = sigmoidf_(sg[k]);
            float fg = sigmoidf_(sg[HH + k]);
            float gg = tanhf_fast(sg[2 * HH + k]);
            float og = sigmoidf_(sg[3 * HH + k]);
            c = fmaf(fg, c, ig * gg);
            float hn = og * tanhf_fast(c);
            sh[k] = hn;
            g_HS[((size_t)b * SS + s) * HH + k] = hn;
        }
        __syncthreads();
        gin0 = gin1; gin1 = gin2;
    }
}

// ---------------- K34: heads + mu linear-recurrence scan (1 block / batch) -
// mu_j = a_j * mu_{j-1} + c_j  composes as (A2,C2)o(A1,C1) = (A2*A1, A2*C1+C2)
__global__ void __launch_bounds__(256) k34_projscan(
        const float* __restrict__ Wmu, const float* __restrict__ bmu,
        const float* __restrict__ Wsig, const float* __restrict__ bsig) {
    const int b    = blockIdx.x;       // 64 blocks
    const int tid  = threadIdx.x;      // 256 threads, 4 consecutive j each
    const int lane = tid & 31;
    const int warp = tid >> 5;
    const int j0   = tid * 4;

    // weights to registers (tiny, L1-resident broadcast)
    float wm0[HH], wm1[HH], wm2[HH], wsg[HH];
#pragma unroll
    for (int m = 0; m < HH; m++) {
        wm0[m] = __ldg(&Wmu[m]);
        wm1[m] = __ldg(&Wmu[HH + m]);
        wm2[m] = __ldg(&Wmu[2 * HH + m]);
        wsg[m] = __ldg(&Wsig[m]);
    }
    const float b0 = __ldg(&bmu[0]), b1 = __ldg(&bmu[1]), b2 = __ldg(&bmu[2]);
    const float bs = __ldg(&bsig[0]);

    float av[4], cv[4];
#pragma unroll
    for (int q = 0; q < 4; q++) {
        const int j = j0 + q;
        const float* h = g_HS + ((size_t)b * SS + j) * HH;
        float d0 = b0, d1 = b1, d2 = b2, ds = bs;
#pragma unroll
        for (int m = 0; m < HH; m++) {
            float hv = h[m];
            d0 = fmaf(wm0[m], hv, d0);
            d1 = fmaf(wm1[m], hv, d1);
            d2 = fmaf(wm2[m], hv, d2);
            ds = fmaf(wsg[m], hv, ds);
        }
        av[q] = fmaxf(d0, 0.0f);
        float m1 = fmaxf(d1, 0.0f);
        float m2 = fmaxf(d2, 0.0f);
        cv[q] = m1 * (1.0f / SS) + m2 * ((float)(j + 1) * (1.0f / SS));
        g_Sig[(size_t)b * SS + j] = sigmoidf_(ds);
    }

    // thread-local composite over 4 elements (in j order)
    float A = av[0], C = cv[0];
#pragma unroll
    for (int q = 1; q < 4; q++) {
        C = fmaf(av[q], C, cv[q]);
        A = av[q] * A;
    }

    // warp inclusive scan of composites
#pragma unroll
    for (int d = 1; d < 32; d <<= 1) {
        float Ap = __shfl_up_sync(0xffffffffu, A, d);
        float Cp = __shfl_up_sync(0xffffffffu, C, d);
        if (lane >= d) { C = fmaf(A, Cp, C); A = A * Ap; }
    }

    __shared__ float sA[8], sC[8];   // warp totals
    __shared__ float wAp[8], wCp[8]; // exclusive warp prefixes
    if (lane == 31) { sA[warp] = A; sC[warp] = C; }

    // thread-exclusive-within-warp composite
    float Aexc = __shfl_up_sync(0xffffffffu, A, 1);
    float Cexc = __shfl_up_sync(0xffffffffu, C, 1);
    if (lane == 0) { Aexc = 1.0f; Cexc = 0.0f; }

    __syncthreads();
    if (tid == 0) {
        float pA = 1.0f, pC = 0.0f;
        for (int wI = 0; wI < 8; wI++) {
            wAp[wI] = pA; wCp[wI] = pC;
            float nC = fmaf(sA[wI], pC, sC[wI]);
            pA = sA[wI] * pA;
            pC = nC;
        }
    }
    __syncthreads();

    // total exclusive prefix: warp prefix first, then in-warp exclusive
    float PC = fmaf(Aexc, wCp[warp], Cexc);
    // mu entering this thread's first element (mu0 = 0 -> just PC)
    float mu = PC;
#pragma unroll
    for (int q = 0; q < 4; q++) {
        mu = fmaf(av[q], mu, cv[q]);
        g_Mu[(size_t)b * SS + j0 + q] = mu;
    }
}

// ---------------- K5: triangular weighted sum + L2 normalization -----------
// grid (16, 64): blockIdx.y = b, j-tile index = 15 - blockIdx.x (heavy first)
__global__ void __launch_bounds__(256) k5_attn(const float* __restrict__ x,
                                               float* __restrict__ out) {
    __shared__ __align__(16) float xs[64][128];   // 32 KB
    __shared__ __align__(16) float ws[64][64];    // 16 KB  (total = 48 KB)

    const int tid = threadIdx.x;
    const int b   = blockIdx.y;
    const int jt  = (int)gridDim.x - 1 - (int)blockIdx.x;
    const int j0  = jt * 64;

    const int wj    = tid & 63;
    const int chunk = tid >> 6;            // 0..3, each covers 16 t's per tile
    const int jg    = j0 + wj;
    const float mu     = g_Mu[(size_t)b * SS + jg];
    const float sgv    = g_Sig[(size_t)b * SS + jg];
    const float inv2s2 = 1.0f / (2.0f * sgv * sgv);
    const float invj1  = 1.0f / (float)(jg + 1);
    float w2 = 0.0f;

    const int jl0 = (tid & 15) * 4;
    const int dd0 = (tid >> 4) * 8;
    float acc[4][8];
#pragma unroll
    for (int i = 0; i < 4; i++)
#pragma unroll
        for (int j = 0; j < 8; j++) acc[i][j] = 0.0f;

    const float4* xg4 = (const float4*)(x + (size_t)b * SS * DD);

    for (int tt = 0; tt <= jt; tt++) {
        const int t0 = tt * 64;
        __syncthreads();

#pragma unroll
        for (int i = 0; i < 8; i++) {
            int idx = tid + i * 256;
            ((float4*)xs)[idx] = xg4[t0 * 32 + idx];
        }
#pragma unroll
        for (int it = 0; it < 16; it++) {
            int tl = chunk * 16 + it;
            int t  = t0 + tl;
            float dlt = fmaf((float)t, invj1, -mu);
            float e   = dlt * dlt * inv2s2;
            float wv  = (t <= jg) ? __expf(-e) : 0.0f;
            ws[tl][wj] = wv;
            w2 = fmaf(wv, wv, w2);
        }
        __syncthreads();

#pragma unroll 8
        for (int t = 0; t < 64; t++) {
            float4 wv = *(const float4*)&ws[t][jl0];
            float4 x0 = *(const float4*)&xs[t][dd0];
            float4 x1 = *(const float4*)&xs[t][dd0 + 4];
            float wr[4] = {wv.x, wv.y, wv.z, wv.w};
            float xr[8] = {x0.x, x0.y, x0.z, x0.w, x1.x, x1.y, x1.z, x1.w};
#pragma unroll
            for (int jj = 0; jj < 4; jj++)
#pragma unroll
                for (int dd = 0; dd < 8; dd++)
                    acc[jj][dd] = fmaf(wr[jj], xr[dd], acc[jj][dd]);
        }
    }

    __syncthreads();
    float* w2p = &ws[0][0];
    w2p[chunk * 64 + wj] = w2;
    __syncthreads();

#pragma unroll
    for (int jj = 0; jj < 4; jj++) {
        int jl = jl0 + jj;
        float s2  = w2p[jl] + w2p[64 + jl] + w2p[128 + jl] + w2p[192 + jl];
        float inv = 1.0f / fmaxf(sqrtf(s2), 1e-12f);
        float4 o0, o1;
        o0.x = acc[jj][0] * inv; o0.y = acc[jj][1] * inv;
        o0.z = acc[jj][2] * inv; o0.w = acc[jj][3] * inv;
        o1.x = acc[jj][4] * inv; o1.y = acc[jj][5] * inv;
        o1.z = acc[jj][6] * inv; o1.w = acc[jj][7] * inv;
        size_t base = ((size_t)b * SS + (j0 + jl)) * DD + dd0;
        *(float4*)&out[base]     = o0;
        *(float4*)&out[base + 4] = o1;
    }
}

// ---------------- launch ---------------------------------------------------
extern "C" void kernel_launch(void* const* d_in, const int* in_sizes, int n_in,
                              void* d_out, int out_size) {
    const float* x    = (const float*)d_in[0];
    const float* Wih  = (const float*)d_in[1];
    const float* Whh  = (const float*)d_in[2];
    const float* bih  = (const float*)d_in[3];
    const float* bhh  = (const float*)d_in[4];
    const float* Wmu  = (const float*)d_in[5];
    const float* bmu  = (const float*)d_in[6];
    const float* Wsig = (const float*)d_in[7];
    const float* bsig = (const float*)d_in[8];
    float* out = (float*)d_out;

    k1_ingemm<<<(BB * SS) / 64, 256>>>(x, Wih, bih, bhh);
    k2_lstm<<<BB, 128>>>(Whh);
    k34_projscan<<<BB, 256>>>(Wmu, bmu, Wsig, bsig);
    k5_attn<<<dim3(SS / 64, BB), 256>>>(x, out);
}